// round 1
// baseline (speedup 1.0000x reference)
#include <cuda_runtime.h>

// Problem shape (fixed by the dataset): u (B=64, L=8192), ev (K=32, L), lam (K)
#define L      8192
#define LMASK  8191
#define NB     64
#define NK     32

// Scratch (no allocs allowed): device globals.
__device__ float g_cot[L];        // cot(pi*l/L) for odd l, 0 for even (used by k_ac)
__device__ float g_cot_odd[L/2];  // cot(pi*(2k+1)/L), k = 0..L/2-1 (used by k_Qout)
__device__ float g_P[L];          // P[l]   = sum_k lam_k * ev[k][l]
__device__ float g_a[NB];         // a_b = Re(sum_i rfft(u)[b,i])
__device__ float g_c[NB];         // c_b = Im(sum_i rfft(u)[b,i])

// ---------------------------------------------------------------------------
// Tables: cot(pi*d/L) in double precision (fp32 arg reduction near pi loses
// ~1e-3 relative on the ~2600-magnitude near-Nyquist values).
__global__ void k_tables() {
    int l = blockIdx.x * blockDim.x + threadIdx.x;
    if (l >= L) return;
    float v = 0.0f;
    if (l & 1) {
        double x = (double)l / (double)L;
        v = (float)(cospi(x) / sinpi(x));
    }
    g_cot[l] = v;
    if (l < L / 2) {
        int d = 2 * l + 1;
        double x = (double)d / (double)L;
        g_cot_odd[l] = (float)(cospi(x) / sinpi(x));
    }
}

// ---------------------------------------------------------------------------
// P[l] = sum_k lam[k] * ev[k*L + l]
__global__ void k_P(const float* __restrict__ ev, const float* __restrict__ lam) {
    int l = blockIdx.x * blockDim.x + threadIdx.x;
    if (l >= L) return;
    float s = 0.0f;
#pragma unroll
    for (int k = 0; k < NK; k++)
        s = fmaf(lam[k], ev[k * L + l], s);
    g_P[l] = s;
}

// ---------------------------------------------------------------------------
// Per-batch scalars:
//   a_b = sum_{l even} u[b,l] + (L/2)*u[b,0]           (so u[b,0] coeff = L/2+1)
//   c_b = -sum_{l odd}  u[b,l] * cot(pi*l/L)
// One block per b; stride 256 keeps each thread on a single parity.
__global__ void k_ac(const float* __restrict__ u) {
    __shared__ double sa[256];
    __shared__ double sc[256];
    const int b = blockIdx.x;
    const int t = threadIdx.x;
    const float* ub = u + (size_t)b * L;

    double a = 0.0, c = 0.0;
    if (t & 1) {
        for (int l = t; l < L; l += 256)
            c -= (double)ub[l] * (double)g_cot[l];
    } else {
        for (int l = t; l < L; l += 256)
            a += (double)ub[l];
    }
    if (t == 0) a += (double)(L / 2) * (double)ub[0];

    sa[t] = a; sc[t] = c;
    __syncthreads();
    for (int s = 128; s > 0; s >>= 1) {
        if (t < s) { sa[t] += sa[t + s]; sc[t] += sc[t + s]; }
        __syncthreads();
    }
    if (t == 0) { g_a[b] = (float)sa[0]; g_c[b] = (float)sc[0]; }
}

// ---------------------------------------------------------------------------
// Q[l] = (2/L) * sum_{k=0}^{L/2-1} cot(pi*(2k+1)/L) * (P[(l+d)&M] - P[(l-d)&M]),
// d = 2k+1. Then out[b, l] = a_b * P[l] + c_b * Q[l].
// Block: 32 l-values, 256 threads; thread t = (j, ly), j = d-chunk (8x256),
// ly = l offset. Warp-uniform d -> g_cot_odd load broadcasts; consecutive ly
// -> conflict-free LDS on P.
__global__ void k_Qout(float* __restrict__ out) {
    __shared__ float Ps[L];        // 32 KB
    __shared__ float qpart[256];
    __shared__ float Qs[32];

    const int t  = threadIdx.x;
    const int l0 = blockIdx.x * 32;

    for (int i = t; i < L; i += 256) Ps[i] = g_P[i];
    __syncthreads();

    const int j  = t >> 5;     // 0..7
    const int ly = t & 31;
    const int l  = l0 + ly;
    const int kbase = j * 256;

    float q = 0.0f;
#pragma unroll 8
    for (int it = 0; it < 256; it++) {
        int kk = kbase + it;
        int d  = 2 * kk + 1;
        float ct = __ldg(&g_cot_odd[kk]);                  // warp-uniform, L1 hot
        q = fmaf(ct, Ps[(l + d) & LMASK] - Ps[(l - d) & LMASK], q);
    }
    qpart[t] = q;
    __syncthreads();

    if (t < 32) {
        float s = 0.0f;
#pragma unroll
        for (int jj = 0; jj < 8; jj++) s += qpart[jj * 32 + t];
        Qs[t] = s * (2.0f / (float)L);
    }
    __syncthreads();

    // 64 b x 32 l outputs per block, 8 per thread, coalesced in l.
#pragma unroll
    for (int r = 0; r < 8; r++) {
        int idx = r * 256 + t;
        int b   = idx >> 5;
        int ll  = idx & 31;
        out[(size_t)b * L + l0 + ll] =
            fmaf(g_a[b], Ps[l0 + ll], g_c[b] * Qs[ll]);
    }
}

// ---------------------------------------------------------------------------
extern "C" void kernel_launch(void* const* d_in, const int* in_sizes, int n_in,
                              void* d_out, int out_size) {
    const float* u   = (const float*)d_in[0];  // (64, 8192)
    const float* ev  = (const float*)d_in[1];  // (32, 8192)
    const float* lam = (const float*)d_in[2];  // (32,)
    float* out = (float*)d_out;                // (64, 8192)

    k_tables<<<(L + 255) / 256, 256>>>();
    k_P<<<(L + 255) / 256, 256>>>(ev, lam);
    k_ac<<<NB, 256>>>(u);
    k_Qout<<<L / 32, 256>>>(out);
}

// round 2
// speedup vs baseline: 1.2510x; 1.2510x over previous
#include <cuda_runtime.h>

// Shapes fixed by the dataset: u (B=64, L=8192), ev (K=32, L), lam (K)
#define L      8192
#define NB     64
#define NK     32
#define HALF   4096   // L/2
#define KD     2048   // number of odd d < L/2

// Device scratch (no allocs allowed)
__device__ float g_cot[L];     // cot(pi*l/L) for odd l, 0 for even (for a/c)
__device__ float g_ct2[KD];    // (2/L)*cot(pi*(2k+1)/L), k<2048 (for Q)
__device__ float g_P[L];       // P[l] = sum_k lam_k ev[k][l]
__device__ float g_Po[HALF];   // P at odd l:  g_Po[m] = P[2m+1]
__device__ float g_Pe[HALF];   // P at even l: g_Pe[m] = P[2m]
__device__ float g_Q[L];       // Q = (2/L) sum_{d odd<L/2} cot(pi d/L)(P[l+d]-P[l-d])
__device__ float g_a[NB];      // Re(sum_i rfft(u)[b,i])
__device__ float g_c[NB];      // Im(sum_i rfft(u)[b,i])

// ---------------------------------------------------------------------------
// k1: P[l], parity-split copies, cot tables. Grid 32x256.
__global__ void k_prep(const float* __restrict__ ev, const float* __restrict__ lam) {
    int l = blockIdx.x * 256 + threadIdx.x;

    float s = 0.0f;
#pragma unroll
    for (int k = 0; k < NK; k++)
        s = fmaf(__ldg(lam + k), __ldg(ev + k * L + l), s);
    g_P[l] = s;
    if (l & 1) g_Po[l >> 1] = s; else g_Pe[l >> 1] = s;

    // cot tables (sinpif/cospif do exact pi-multiple reduction: ~1-2 ulp)
    float ct = 0.0f;
    if (l & 1) {
        float x = (float)l * (1.0f / (float)L);
        ct = cospif(x) / sinpif(x);
    }
    g_cot[l] = ct;

    if (l < KD) {
        float x = (float)(2 * l + 1) * (1.0f / (float)L);
        g_ct2[l] = (2.0f / (float)L) * (cospif(x) / sinpif(x));
    }
}

// ---------------------------------------------------------------------------
// k2: heterogeneous. Blocks 0..63: per-batch scalars a_b, c_b.
//     Blocks 64..319: Q[l] for 32 same-parity l's each.
// 512 threads per block.
__global__ void __launch_bounds__(512) k_mid(const float* __restrict__ u) {
    __shared__ float  Pd[2 * HALF];   // duplicated parity-half of P (32 KB)
    __shared__ float  red[512];
    __shared__ double da[512];
    __shared__ double dc[512];

    const int t  = threadIdx.x;
    const int bx = blockIdx.x;

    if (bx < NB) {
        // ---- a/c reduction for batch b = bx ----
        const int b = bx;
        const float4* u4  = (const float4*)(u + (size_t)b * L);
        const float4* ct4 = (const float4*)g_cot;
        double a = 0.0, c = 0.0;
#pragma unroll
        for (int r = 0; r < 4; r++) {
            int i = r * 512 + t;            // i < 2048 float4s
            float4 uv = u4[i];
            float4 cv = ct4[i];             // .x,.z are zero entries
            a += (double)uv.x + (double)uv.z;
            c -= (double)uv.y * (double)cv.y + (double)uv.w * (double)cv.w;
        }
        if (t == 0) a += (double)(L / 2) * (double)u[(size_t)b * L];
        da[t] = a; dc[t] = c;
        __syncthreads();
        for (int s = 256; s > 0; s >>= 1) {
            if (t < s) { da[t] += da[t + s]; dc[t] += dc[t + s]; }
            __syncthreads();
        }
        if (t == 0) { g_a[b] = (float)da[0]; g_c[b] = (float)dc[0]; }
        return;
    }

    // ---- Q blocks ----
    const int qb = bx - NB;            // 0..255
    const int p  = qb >> 7;            // 0: even-l block, 1: odd-l block
    const int m0 = (qb & 127) * 32;    // 32 m-values per block

    // Stage the needed parity half of P, duplicated so indices [0, 2*HALF) are
    // mask-free for both +k and -k directions.
    const float* src = p ? g_Pe : g_Po;
    for (int i = t; i < HALF; i += 512) {
        float v = src[i];
        Pd[i] = v;
        Pd[i + HALF] = v;
    }
    __syncthreads();

    const int ly = t & 31;             // which m in this block
    const int j  = t >> 5;             // 0..15 k-chunks of 128
    const int m  = m0 + ly;
    const int kbase = j * 128;

    // even l=2m:  P[l+d]=Po[m+k],   P[l-d]=Po[m-k-1]  (d=2k+1)
    // odd  l=2m+1:P[l+d]=Pe[m+k+1], P[l-d]=Pe[m-k]
    const int sA = p ? 1 : 0;
    const int sB = p ? HALF : (HALF - 1);
    const float* pA = Pd + m + kbase + sA;
    const float* pB = Pd + m - kbase + sB - 127;   // pB[127-kk] = Pd[m-(kbase+kk)+sB]
    const float* ct = g_ct2 + kbase;

    float q = 0.0f;
#pragma unroll 16
    for (int kk = 0; kk < 128; kk++)
        q = fmaf(__ldg(ct + kk), pA[kk] - pB[127 - kk], q);

    red[t] = q;
    __syncthreads();
    if (t < 32) {
        float s = 0.0f;
#pragma unroll
        for (int jj = 0; jj < 16; jj++) s += red[jj * 32 + t];
        g_Q[2 * (m0 + t) + p] = s;     // ct2 already carries the 2/L factor
    }
}

// ---------------------------------------------------------------------------
// k3: out[b,l] = a_b * P[l] + c_b * Q[l], fully coalesced float4.
// Grid 512x256: one float4 per thread.
__global__ void k_out(float* __restrict__ out) {
    int gid = blockIdx.x * 256 + threadIdx.x;   // 0 .. 131071
    int b   = gid >> 11;                        // 2048 float4 per row
    int l4  = gid & 2047;
    float a = g_a[b];
    float c = g_c[b];
    float4 P = ((const float4*)g_P)[l4];
    float4 Q = ((const float4*)g_Q)[l4];
    float4 o;
    o.x = fmaf(a, P.x, c * Q.x);
    o.y = fmaf(a, P.y, c * Q.y);
    o.z = fmaf(a, P.z, c * Q.z);
    o.w = fmaf(a, P.w, c * Q.w);
    ((float4*)out)[gid] = o;
}

// ---------------------------------------------------------------------------
extern "C" void kernel_launch(void* const* d_in, const int* in_sizes, int n_in,
                              void* d_out, int out_size) {
    const float* u   = (const float*)d_in[0];  // (64, 8192)
    const float* ev  = (const float*)d_in[1];  // (32, 8192)
    const float* lam = (const float*)d_in[2];  // (32,)
    float* out = (float*)d_out;                // (64, 8192)

    k_prep<<<L / 256, 256>>>(ev, lam);
    k_mid <<<NB + 256, 512>>>(u);
    k_out <<<(NB * L) / (4 * 256), 256>>>(out);
}

// round 3
// speedup vs baseline: 1.5179x; 1.2133x over previous
#include <cuda_runtime.h>

// Shapes fixed by the dataset: u (B=64, L=8192), ev (K=32, L), lam (K)
#define L      8192
#define NB     64
#define NK     32
#define HALF   4096   // L/2
#define KD     2048   // number of odd d < L/2
#define SPL    4      // partial-sum splits per batch row (a/c)

// Device scratch (no allocs allowed)
__device__ float  g_ct2[KD];      // (2/L)*cot(pi*(2k+1)/L)
__device__ float  g_P[L];         // P[l] = sum_k lam_k ev[k][l]
__device__ float  g_Po[HALF];     // P at odd l
__device__ float  g_Pe[HALF];     // P at even l
__device__ double g_pa[NB * SPL]; // partial Re-sums
__device__ double g_pc[NB * SPL]; // partial Im-sums

// ---------------------------------------------------------------------------
// k1, heterogeneous:
//  blocks [0, 256):  a/c partials. Block (b, s) reduces 2048 floats of u[b].
//     a_b = sum_{l even} u[b,l] + (L/2)*u[b,0]
//     c_b = -sum_{l odd}  u[b,l] * cot(pi*l/L)   (cot computed inline)
//  blocks [256,384): P. One warp per float4-of-l, lane = k; shfl reduce.
//     Also fills the parity-split copies and the ct2 table.
__global__ void __launch_bounds__(512) k1(const float* __restrict__ u,
                                          const float* __restrict__ ev,
                                          const float* __restrict__ lam) {
    const int t  = threadIdx.x;
    const int bx = blockIdx.x;

    if (bx < NB * SPL) {
        __shared__ double sa[512], sc[512];
        const int b = bx >> 2, s = bx & 3;
        const int i = s * 512 + t;                 // float4 index within row
        float4 uv = ((const float4*)(u + (size_t)b * L))[i];
        // odd l's covered by this float4: 4i+1, 4i+3
        float x1 = (float)(4 * i + 1) * (1.0f / (float)L);
        float x3 = (float)(4 * i + 3) * (1.0f / (float)L);
        float c1 = cospif(x1) / sinpif(x1);
        float c3 = cospif(x3) / sinpif(x3);
        double a = (double)uv.x + (double)uv.z;
        double c = -((double)uv.y * (double)c1 + (double)uv.w * (double)c3);
        if (i == 0) a += (double)(L / 2) * (double)uv.x;
        sa[t] = a; sc[t] = c;
        __syncthreads();
        for (int r = 256; r > 0; r >>= 1) {
            if (t < r) { sa[t] += sa[t + r]; sc[t] += sc[t + r]; }
            __syncthreads();
        }
        if (t == 0) { g_pa[bx] = sa[0]; g_pc[bx] = sc[0]; }
        return;
    }

    // ---- P blocks ----
    const int pb = bx - NB * SPL;       // 0..127
    const int l4 = pb * 16 + (t >> 5);  // float4-of-l index (0..2047)
    const int k  = t & 31;              // eigenvector row
    float4 e  = ((const float4*)ev)[k * (L / 4) + l4];
    float  lk = __ldg(lam + k);
    float4 v; v.x = lk * e.x; v.y = lk * e.y; v.z = lk * e.z; v.w = lk * e.w;
#pragma unroll
    for (int off = 16; off > 0; off >>= 1) {
        v.x += __shfl_down_sync(0xffffffffu, v.x, off);
        v.y += __shfl_down_sync(0xffffffffu, v.y, off);
        v.z += __shfl_down_sync(0xffffffffu, v.z, off);
        v.w += __shfl_down_sync(0xffffffffu, v.w, off);
    }
    if (k == 0) {
        ((float4*)g_P)[l4] = v;
        g_Pe[2 * l4]     = v.x;  g_Po[2 * l4]     = v.y;
        g_Pe[2 * l4 + 1] = v.z;  g_Po[2 * l4 + 1] = v.w;
    }
    if (t < 16) {
        int idx = pb * 16 + t;          // 0..2047
        float x = (float)(2 * idx + 1) * (1.0f / (float)L);
        g_ct2[idx] = (2.0f / (float)L) * (cospif(x) / sinpif(x));
    }
}

// ---------------------------------------------------------------------------
// k2: 256 blocks; block qb owns 32 same-parity l's (p = qb>>7, m0 = (qb&127)*32).
// Computes Q[l] = sum_{d odd < L/2} ct2 * (P[l+d] - P[l-d]) via the duplicated
// opposite-parity half of P in smem, then writes out[b,l] = a_b P[l] + c_b Q[l]
// for ALL 64 batches directly (no third kernel).
__global__ void __launch_bounds__(512) k2(float* __restrict__ out) {
    __shared__ float Pd[2 * HALF];      // 32 KB, duplicated parity half
    __shared__ float red[512];
    __shared__ float aS[NB], cS[NB], Qs[32], Ps[32];

    const int t  = threadIdx.x;
    const int qb = blockIdx.x;
    const int p  = qb >> 7;             // 0: even l, 1: odd l
    const int m0 = (qb & 127) * 32;

    const float* src = p ? g_Pe : g_Po; // opposite parity (odd distances)
    for (int i = t; i < HALF; i += 512) {
        float v = src[i];
        Pd[i] = v; Pd[i + HALF] = v;
    }
    if (t < NB) {
        double a = 0.0, c = 0.0;
#pragma unroll
        for (int s = 0; s < SPL; s++) { a += g_pa[t * SPL + s]; c += g_pc[t * SPL + s]; }
        aS[t] = (float)a; cS[t] = (float)c;
    } else if (t < NB + 32) {
        int ly = t - NB;
        Ps[ly] = g_P[2 * (m0 + ly) + p];   // same-parity P for the output combine
    }
    __syncthreads();

    const int ly = t & 31;
    const int j  = t >> 5;              // 0..15 k-chunks of 128
    const int m  = m0 + ly;
    const int kbase = j * 128;

    // even l=2m:   P[l+d]=Po[m+k],   P[l-d]=Po[m-k-1]  (d=2k+1)
    // odd  l=2m+1: P[l+d]=Pe[m+k+1], P[l-d]=Pe[m-k]
    const int sA = p ? 1 : 0;
    const int sB = p ? HALF : (HALF - 1);
    const float* pA = Pd + m + kbase + sA;
    const float* pB = Pd + m - kbase + sB - 127;    // pB[127-kk] = Pd[m-(kbase+kk)+sB]
    const float* ct = g_ct2 + kbase;

    float q = 0.0f;
#pragma unroll 16
    for (int kk = 0; kk < 128; kk++)
        q = fmaf(__ldg(ct + kk), pA[kk] - pB[127 - kk], q);

    red[t] = q;
    __syncthreads();
    if (t < 32) {
        float s = 0.0f;
#pragma unroll
        for (int jj = 0; jj < 16; jj++) s += red[jj * 32 + t];
        Qs[t] = s;                       // ct2 already carries 2/L
    }
    __syncthreads();

    // 64 b x 32 l outputs, 4 per thread (stride-2 in l, consecutive ly per warp)
#pragma unroll
    for (int r = 0; r < 4; r++) {
        int idx = r * 512 + t;
        int b   = idx >> 5;
        int ll  = idx & 31;
        out[(size_t)b * L + 2 * (m0 + ll) + p] =
            fmaf(aS[b], Ps[ll], cS[b] * Qs[ll]);
    }
}

// ---------------------------------------------------------------------------
extern "C" void kernel_launch(void* const* d_in, const int* in_sizes, int n_in,
                              void* d_out, int out_size) {
    const float* u   = (const float*)d_in[0];  // (64, 8192)
    const float* ev  = (const float*)d_in[1];  // (32, 8192)
    const float* lam = (const float*)d_in[2];  // (32,)
    float* out = (float*)d_out;                // (64, 8192)

    k1<<<NB * SPL + 128, 512>>>(u, ev, lam);
    k2<<<256, 512>>>(out);
}

// round 5
// speedup vs baseline: 1.5563x; 1.0253x over previous
#include <cuda_runtime.h>

// Shapes fixed by the dataset: u (B=64, L=8192), ev (K=32, L), lam (K)
#define L      8192
#define NB     64
#define NK     32
#define HALF   4096   // L/2
#define KD     2048   // number of odd d < L/2
#define SPL    4      // partial-sum splits per batch row (a/c)

// Device scratch (no allocs allowed)
__device__ float  g_ct2[KD];      // (2/L)*cot(pi*(2k+1)/L)
__device__ float  g_P[L];         // P[l] = sum_k lam_k ev[k][l]
__device__ float  g_Po[HALF];     // P at odd l
__device__ float  g_Pe[HALF];     // P at even l
__device__ double g_pa[NB * SPL]; // partial Re-sums
__device__ double g_pc[NB * SPL]; // partial Im-sums

// ---------------------------------------------------------------------------
// k1, heterogeneous:
//  blocks [0, 256):  a/c partials. Block (b, s) reduces 2048 floats of u[b].
//     a_b = sum_{l even} u[b,l] + (L/2)*u[b,0]
//     c_b = -sum_{l odd}  u[b,l] * cot(pi*l/L)   (cot computed inline)
//  blocks [256,384): P. One warp per float4-of-l, lane = k; shfl reduce.
//     Also fills the parity-split copies and the ct2 table.
__global__ void __launch_bounds__(512) k1(const float* __restrict__ u,
                                          const float* __restrict__ ev,
                                          const float* __restrict__ lam) {
    const int t  = threadIdx.x;
    const int bx = blockIdx.x;

    if (bx < NB * SPL) {
        __shared__ double sa[512], sc[512];
        const int b = bx >> 2, s = bx & 3;
        const int i = s * 512 + t;                 // float4 index within row
        float4 uv = ((const float4*)(u + (size_t)b * L))[i];
        // odd l's covered by this float4: 4i+1, 4i+3
        float x1 = (float)(4 * i + 1) * (1.0f / (float)L);
        float x3 = (float)(4 * i + 3) * (1.0f / (float)L);
        float c1 = cospif(x1) / sinpif(x1);
        float c3 = cospif(x3) / sinpif(x3);
        double a = (double)uv.x + (double)uv.z;
        double c = -((double)uv.y * (double)c1 + (double)uv.w * (double)c3);
        if (i == 0) a += (double)(L / 2) * (double)uv.x;
        sa[t] = a; sc[t] = c;
        __syncthreads();
        for (int r = 256; r > 0; r >>= 1) {
            if (t < r) { sa[t] += sa[t + r]; sc[t] += sc[t + r]; }
            __syncthreads();
        }
        if (t == 0) { g_pa[bx] = sa[0]; g_pc[bx] = sc[0]; }
        return;
    }

    // ---- P blocks ----
    const int pb = bx - NB * SPL;       // 0..127
    const int l4 = pb * 16 + (t >> 5);  // float4-of-l index (0..2047)
    const int k  = t & 31;              // eigenvector row
    float4 e  = ((const float4*)ev)[k * (L / 4) + l4];
    float  lk = __ldg(lam + k);
    float4 v; v.x = lk * e.x; v.y = lk * e.y; v.z = lk * e.z; v.w = lk * e.w;
#pragma unroll
    for (int off = 16; off > 0; off >>= 1) {
        v.x += __shfl_down_sync(0xffffffffu, v.x, off);
        v.y += __shfl_down_sync(0xffffffffu, v.y, off);
        v.z += __shfl_down_sync(0xffffffffu, v.z, off);
        v.w += __shfl_down_sync(0xffffffffu, v.w, off);
    }
    if (k == 0) {
        ((float4*)g_P)[l4] = v;
        g_Pe[2 * l4]     = v.x;  g_Po[2 * l4]     = v.y;
        g_Pe[2 * l4 + 1] = v.z;  g_Po[2 * l4 + 1] = v.w;
    }
    if (t < 16) {
        int idx = pb * 16 + t;          // 0..2047
        float x = (float)(2 * idx + 1) * (1.0f / (float)L);
        g_ct2[idx] = (2.0f / (float)L) * (cospif(x) / sinpif(x));
    }
}

// ---------------------------------------------------------------------------
// k2: 256 blocks x 1024 threads; block qb owns 32 same-parity l's
// (p = qb>>7, m0 = (qb&127)*32). Thread (j = t>>5 in [0,32), ly = t&31)
// accumulates a 64-wide k-chunk for l = 2*(m0+ly)+p with 4 independent
// accumulators, then block-reduces and writes out[b,l] = a_b*P[l] + c_b*Q[l]
// for all 64 batches (fused output).
__global__ void __launch_bounds__(1024) k2(float* __restrict__ out) {
    __shared__ float Pd[2 * HALF];      // 32 KB, duplicated parity half
    __shared__ float red[1024];
    __shared__ float aS[NB], cS[NB], Qs[32], Ps[32];

    const int t  = threadIdx.x;
    const int qb = blockIdx.x;
    const int p  = qb >> 7;             // 0: even l, 1: odd l
    const int m0 = (qb & 127) * 32;

    // Stage opposite-parity half of P, duplicated (mask-free +/- indexing).
    // All 1024 threads: exactly one float4 each (HALF/4 = 1024).
    {
        const float4* src4 = (const float4*)(p ? g_Pe : g_Po);
        float4 v = src4[t];
        ((float4*)Pd)[t] = v;
        ((float4*)(Pd + HALF))[t] = v;
    }
    // Scalars: first 96 threads ALSO do this (bugfix vs previous round's dead else).
    if (t < NB) {
        double a = 0.0, c = 0.0;
#pragma unroll
        for (int s = 0; s < SPL; s++) { a += g_pa[t * SPL + s]; c += g_pc[t * SPL + s]; }
        aS[t] = (float)a; cS[t] = (float)c;
    } else if (t < NB + 32) {
        int ly = t - NB;
        Ps[ly] = g_P[2 * (m0 + ly) + p];  // same-parity P for output combine
    }
    __syncthreads();

    const int ly = t & 31;
    const int j  = t >> 5;              // 0..31 k-chunks of 64
    const int m  = m0 + ly;
    const int kbase = j * 64;

    // even l=2m:   P[l+d]=Po[m+k],   P[l-d]=Po[m-k-1]  (d=2k+1)
    // odd  l=2m+1: P[l+d]=Pe[m+k+1], P[l-d]=Pe[m-k]
    const int sA = p ? 1 : 0;
    const int sB = p ? HALF : (HALF - 1);
    const float* pA = Pd + m + kbase + sA;
    const float* pB = Pd + m - kbase + sB - 63;    // pB[63-kk] = Pd[m-(kbase+kk)+sB]
    const float* ct = g_ct2 + kbase;

    float q0 = 0.0f, q1 = 0.0f, q2 = 0.0f, q3 = 0.0f;
#pragma unroll
    for (int kk = 0; kk < 64; kk += 4) {
        q0 = fmaf(__ldg(ct + kk + 0), pA[kk + 0] - pB[63 - kk], q0);
        q1 = fmaf(__ldg(ct + kk + 1), pA[kk + 1] - pB[62 - kk], q1);
        q2 = fmaf(__ldg(ct + kk + 2), pA[kk + 2] - pB[61 - kk], q2);
        q3 = fmaf(__ldg(ct + kk + 3), pA[kk + 3] - pB[60 - kk], q3);
    }
    red[t] = (q0 + q1) + (q2 + q3);
    __syncthreads();

    if (t < 32) {
        float s = 0.0f;
#pragma unroll
        for (int jj = 0; jj < 32; jj++) s += red[jj * 32 + t];
        Qs[t] = s;                       // ct2 already carries 2/L
    }
    __syncthreads();

    // 64 b x 32 l outputs, 2 per thread
#pragma unroll
    for (int r = 0; r < 2; r++) {
        int idx = r * 1024 + t;
        int b   = idx >> 5;
        int ll  = idx & 31;
        out[(size_t)b * L + 2 * (m0 + ll) + p] =
            fmaf(aS[b], Ps[ll], cS[b] * Qs[ll]);
    }
}

// ---------------------------------------------------------------------------
extern "C" void kernel_launch(void* const* d_in, const int* in_sizes, int n_in,
                              void* d_out, int out_size) {
    const float* u   = (const float*)d_in[0];  // (64, 8192)
    const float* ev  = (const float*)d_in[1];  // (32, 8192)
    const float* lam = (const float*)d_in[2];  // (32,)
    float* out = (float*)d_out;                // (64, 8192)

    k1<<<NB * SPL + 128, 512>>>(u, ev, lam);
    k2<<<256, 1024>>>(out);
}

// round 6
// speedup vs baseline: 3.0246x; 1.9435x over previous
#include <cuda_runtime.h>

// Shapes fixed by the dataset: u (B=64, L=8192), ev (K=32, L), lam (K)
#define L      8192
#define NB     64
#define NK     32
#define HALF   4096   // L/2
#define KD     2048   // number of odd d < L/2
#define SPL    4      // partial-sum splits per batch row (a/c)

// Device scratch (no allocs allowed)
__device__ float g_ct2[KD];      // (2/L)*cot(pi*(2k+1)/L)
__device__ float g_P[L];         // P[l] = sum_k lam_k ev[k][l]
__device__ float g_Po[HALF];     // P at odd l
__device__ float g_Pe[HALF];     // P at even l
__device__ float g_pa[NB * SPL]; // partial Re-sums
__device__ float g_pc[NB * SPL]; // partial Im-sums

// ---------------------------------------------------------------------------
// k1, heterogeneous:
//  blocks [0,256):  a/c partials, float + warp shuffles.
//  blocks [256,384): P (warp per float4-of-l, lane = k), parity copies, ct2.
__global__ void __launch_bounds__(512) k1(const float* __restrict__ u,
                                          const float* __restrict__ ev,
                                          const float* __restrict__ lam) {
    const int t  = threadIdx.x;
    const int bx = blockIdx.x;

    if (bx < NB * SPL) {
        __shared__ float wa[16], wc[16];
        const int b = bx >> 2, sp = bx & 3;
        const int i = sp * 512 + t;                // float4 index within row
        float4 uv = ((const float4*)(u + (size_t)b * L))[i];
        float x1 = (float)(4 * i + 1) * (1.0f / (float)L);
        float x3 = (float)(4 * i + 3) * (1.0f / (float)L);
        float c1 = __fdividef(cospif(x1), sinpif(x1));
        float c3 = __fdividef(cospif(x3), sinpif(x3));
        float a = uv.x + uv.z;
        float c = -(uv.y * c1 + uv.w * c3);
        if (i == 0) a += (float)(L / 2) * uv.x;
#pragma unroll
        for (int off = 16; off > 0; off >>= 1) {
            a += __shfl_down_sync(0xffffffffu, a, off);
            c += __shfl_down_sync(0xffffffffu, c, off);
        }
        const int lane = t & 31, w = t >> 5;
        if (lane == 0) { wa[w] = a; wc[w] = c; }
        __syncthreads();
        if (t < 32) {
            float av = (t < 16) ? wa[t] : 0.0f;
            float cv = (t < 16) ? wc[t] : 0.0f;
#pragma unroll
            for (int off = 8; off > 0; off >>= 1) {
                av += __shfl_down_sync(0xffffffffu, av, off);
                cv += __shfl_down_sync(0xffffffffu, cv, off);
            }
            if (t == 0) { g_pa[bx] = av; g_pc[bx] = cv; }
        }
        return;
    }

    // ---- P blocks ----
    const int pb = bx - NB * SPL;       // 0..127
    const int l4 = pb * 16 + (t >> 5);  // float4-of-l index (0..2047)
    const int k  = t & 31;              // eigenvector row
    float4 e  = ((const float4*)ev)[k * (L / 4) + l4];
    float  lk = __ldg(lam + k);
    float4 v; v.x = lk * e.x; v.y = lk * e.y; v.z = lk * e.z; v.w = lk * e.w;
#pragma unroll
    for (int off = 16; off > 0; off >>= 1) {
        v.x += __shfl_down_sync(0xffffffffu, v.x, off);
        v.y += __shfl_down_sync(0xffffffffu, v.y, off);
        v.z += __shfl_down_sync(0xffffffffu, v.z, off);
        v.w += __shfl_down_sync(0xffffffffu, v.w, off);
    }
    if (k == 0) {
        ((float4*)g_P)[l4] = v;
        g_Pe[2 * l4]     = v.x;  g_Po[2 * l4]     = v.y;
        g_Pe[2 * l4 + 1] = v.z;  g_Po[2 * l4 + 1] = v.w;
    }
    if (t < 16) {
        int idx = pb * 16 + t;          // 0..2047
        float x = (float)(2 * idx + 1) * (1.0f / (float)L);
        g_ct2[idx] = (2.0f / (float)L) * __fdividef(cospif(x), sinpif(x));
    }
}

// ---------------------------------------------------------------------------
// k2: 256 blocks x 1024 threads. Block qb: p = qb>>7 (parity), m0 = (qb&127)*32
// (32 l-values: l = 2*(m0+mm)+p, mm in [0,32)). Register-tiled 4m x 4k:
// thread (ly = t&7, j = t>>3) computes acc[r] for m = m0+4*ly+r over
// k in [16j, 16j+16) via aligned float4 LDS from pre-shifted smem copies.
// Then reduce over j and write out[b,l] = a_b*P[l] + c_b*Q[l] for all b.
__global__ void __launch_bounds__(1024) k2(float* __restrict__ out) {
    __shared__ alignas(16) float SA[2112];
    __shared__ alignas(16) float SB[2112];
    __shared__ alignas(16) float CT[2048];
    __shared__ alignas(16) float red2[32 * 36];
    __shared__ float Ps[32], aS[NB], cS[NB], Qs[32];

    const int t  = threadIdx.x;
    const int qb = blockIdx.x;
    const int p  = qb >> 7;
    const int m0 = (qb & 127) * 32;

    // Stage shifted copies.
    // even (p=0): A = Po[m+k],   B = Po[m-k-1]
    // odd  (p=1): A = Pe[m+k+1], B = Pe[m-k]
    // SA[x] = S[(m0 + p + x) & 4095]        (A index = SA[mm + k])
    // SB[x] = S[(m0 + x - 2052 + p) & 4095] (B index = SB[2048 + mm - k + 3 - ...])
    {
        const float* S = p ? g_Pe : g_Po;
        const int baseA = m0 + p;
        const int baseB = m0 - 2052 + p;
#pragma unroll
        for (int x = t; x < 2112; x += 1024) {
            SA[x] = S[(baseA + x) & (HALF - 1)];
            SB[x] = S[(baseB + x) & (HALF - 1)];
        }
        CT[t]        = g_ct2[t];
        CT[t + 1024] = g_ct2[t + 1024];
    }
    if (t < NB) {
        aS[t] = g_pa[4 * t] + g_pa[4 * t + 1] + g_pa[4 * t + 2] + g_pa[4 * t + 3];
        cS[t] = g_pc[4 * t] + g_pc[4 * t + 1] + g_pc[4 * t + 2] + g_pc[4 * t + 3];
    } else if (t < NB + 32) {
        Ps[t - NB] = g_P[2 * (m0 + t - NB) + p];
    }
    __syncthreads();

    const int ly = t & 7;
    const int j  = t >> 3;              // 0..127, k-range [16j, 16j+16)
    const float4* SA4 = (const float4*)SA;
    const float4* SB4 = (const float4*)SB;
    const float4* CT4 = (const float4*)CT;

    float acc0 = 0.0f, acc1 = 0.0f, acc2 = 0.0f, acc3 = 0.0f;
#pragma unroll
    for (int kt = 0; kt < 4; kt++) {
        const int xa4 = ly + 4 * j + kt;          // float4 index of SA tile base
        const int xb4 = 512 + ly - 4 * j - kt;    // float4 index of SB tile base
        float4 A0 = SA4[xa4], A1 = SA4[xa4 + 1];
        float4 B0 = SB4[xb4], B1 = SB4[xb4 + 1];
        float4 C  = CT4[4 * j + kt];
        float a0 = A0.x, a1 = A0.y, a2 = A0.z, a3 = A0.w;
        float a4 = A1.x, a5 = A1.y, a6 = A1.z;
        float b0 = B0.x, b1 = B0.y, b2 = B0.z, b3 = B0.w;
        float b4 = B1.x, b5 = B1.y, b6 = B1.z;
        // acc[r] += C[s] * (a[r+s] - b[3+r-s])
        acc0 = fmaf(C.x, a0 - b3, acc0);
        acc0 = fmaf(C.y, a1 - b2, acc0);
        acc0 = fmaf(C.z, a2 - b1, acc0);
        acc0 = fmaf(C.w, a3 - b0, acc0);
        acc1 = fmaf(C.x, a1 - b4, acc1);
        acc1 = fmaf(C.y, a2 - b3, acc1);
        acc1 = fmaf(C.z, a3 - b2, acc1);
        acc1 = fmaf(C.w, a4 - b1, acc1);
        acc2 = fmaf(C.x, a2 - b5, acc2);
        acc2 = fmaf(C.y, a3 - b4, acc2);
        acc2 = fmaf(C.z, a4 - b3, acc2);
        acc2 = fmaf(C.w, a5 - b2, acc2);
        acc3 = fmaf(C.x, a3 - b6, acc3);
        acc3 = fmaf(C.y, a4 - b5, acc3);
        acc3 = fmaf(C.z, a5 - b4, acc3);
        acc3 = fmaf(C.w, a6 - b3, acc3);
    }

    // Reduce over the 4 j's inside each warp (lanes lane, lane+8, +16, +24
    // share ly); lanes 0..7 end with the warp's partial for its 4 m's.
    acc0 += __shfl_down_sync(0xffffffffu, acc0, 16);
    acc1 += __shfl_down_sync(0xffffffffu, acc1, 16);
    acc2 += __shfl_down_sync(0xffffffffu, acc2, 16);
    acc3 += __shfl_down_sync(0xffffffffu, acc3, 16);
    acc0 += __shfl_down_sync(0xffffffffu, acc0, 8);
    acc1 += __shfl_down_sync(0xffffffffu, acc1, 8);
    acc2 += __shfl_down_sync(0xffffffffu, acc2, 8);
    acc3 += __shfl_down_sync(0xffffffffu, acc3, 8);

    const int lane = t & 31, w = t >> 5;
    if (lane < 8) {
        float4 v; v.x = acc0; v.y = acc1; v.z = acc2; v.w = acc3;
        ((float4*)(red2 + w * 36 + lane * 4))[0] = v;   // red2[w*36 + m]
    }
    __syncthreads();

    if (t < 32) {
        float s = 0.0f;
#pragma unroll
        for (int w2 = 0; w2 < 32; w2++) s += red2[w2 * 36 + t];
        Qs[t] = s;                       // ct2 already carries 2/L
    }
    __syncthreads();

    // 64 b x 32 l outputs, 2 per thread
#pragma unroll
    for (int r = 0; r < 2; r++) {
        int idx = r * 1024 + t;
        int b   = idx >> 5;
        int ll  = idx & 31;
        out[(size_t)b * L + 2 * (m0 + ll) + p] =
            fmaf(aS[b], Ps[ll], cS[b] * Qs[ll]);
    }
}

// ---------------------------------------------------------------------------
extern "C" void kernel_launch(void* const* d_in, const int* in_sizes, int n_in,
                              void* d_out, int out_size) {
    const float* u   = (const float*)d_in[0];  // (64, 8192)
    const float* ev  = (const float*)d_in[1];  // (32, 8192)
    const float* lam = (const float*)d_in[2];  // (32,)
    float* out = (float*)d_out;                // (64, 8192)

    k1<<<NB * SPL + 128, 512>>>(u, ev, lam);
    k2<<<256, 1024>>>(out);
}